// round 1
// baseline (speedup 1.0000x reference)
#include <cuda_runtime.h>
#include <math.h>

#define BATCH 8
#define NN 262144
#define PRE 6000
#define PROP 1000
#define SEL_CAP 8192

// ---------------- scratch (static device memory; no allocations) ----------------
__device__ unsigned int       g_keys[BATCH * NN];          // 8 MB
__device__ int                g_hist[BATCH * 256];
__device__ unsigned int       g_prefix[BATCH];
__device__ int                g_krem[BATCH];
__device__ int                g_cnt[BATCH];
__device__ unsigned long long g_sel[BATCH * SEL_CAP];      // 512 KB
__device__ float4             g_boxes[BATCH * PRE];        // 768 KB

// order-preserving float -> uint key (works for any sign)
__device__ __forceinline__ unsigned fkey(float f) {
    unsigned u = __float_as_uint(f);
    return u ^ (((unsigned)((int)u >> 31)) | 0x80000000u);
}

// ---------------- init: reset per-launch state ----------------
__global__ void init_k() {
    int t = blockIdx.x * blockDim.x + threadIdx.x;
    if (t < BATCH * 256) g_hist[t] = 0;
    if (t < BATCH) { g_prefix[t] = 0; g_krem[t] = PRE; g_cnt[t] = 0; }
}

// ---------------- pass 0: extract keys + histogram of top byte ----------------
// grid (128, BATCH), 256 threads; each block handles 1024 float4 (=2048 score pairs)
__global__ void extract_hist_k(const float* __restrict__ probs) {
    __shared__ int sh[256];
    int tid = threadIdx.x;
    sh[tid] = 0;
    __syncthreads();
    int b = blockIdx.y;
    const float4* p4 = (const float4*)probs + (size_t)b * (NN / 2);
    uint2* kout = (uint2*)g_keys + (size_t)b * (NN / 2);
#pragma unroll
    for (int t = 0; t < 4; t++) {
        int f = blockIdx.x * 1024 + t * 256 + tid;
        float4 v = p4[f];
        unsigned k0 = fkey(v.y), k1 = fkey(v.w);
        kout[f] = make_uint2(k0, k1);
        atomicAdd(&sh[k0 >> 24], 1);
        atomicAdd(&sh[k1 >> 24], 1);
    }
    __syncthreads();
    if (sh[tid]) atomicAdd(&g_hist[b * 256 + tid], sh[tid]);
}

// ---------------- radix pass histogram (shift in {16,8,0}) ----------------
// grid (64, BATCH), 256 threads; each block handles 1024 uint4 (=4096 keys)
__global__ void hist_k(int shift) {
    __shared__ int sh[256];
    int tid = threadIdx.x;
    sh[tid] = 0;
    __syncthreads();
    int b = blockIdx.y;
    unsigned pref = g_prefix[b];
    unsigned mh = 0xFFFFFFFFu << (shift + 8);   // bits already decided
    const uint4* k4 = (const uint4*)g_keys + (size_t)b * (NN / 4);
#pragma unroll
    for (int t = 0; t < 4; t++) {
        int f = blockIdx.x * 1024 + t * 256 + tid;
        uint4 v = k4[f];
        unsigned a[4] = {v.x, v.y, v.z, v.w};
#pragma unroll
        for (int e = 0; e < 4; e++)
            if ((a[e] & mh) == (pref & mh))
                atomicAdd(&sh[(a[e] >> shift) & 0xFF], 1);
    }
    __syncthreads();
    if (sh[tid]) atomicAdd(&g_hist[b * 256 + tid], sh[tid]);
}

// ---------------- pick bucket containing k-th largest; zero hist for reuse ----------------
__global__ void select_k(int shift) {
    __shared__ int h[256];
    int tid = threadIdx.x;
    for (int b = 0; b < BATCH; b++) {
        h[tid] = g_hist[b * 256 + tid];
        g_hist[b * 256 + tid] = 0;
        __syncthreads();
        if (tid == 0) {
            int krem = g_krem[b], acc = 0, d = 255;
            for (; d > 0; d--) {
                int c = h[d];
                if (acc + c >= krem) break;
                acc += c;
            }
            g_krem[b] = krem - acc;
            g_prefix[b] |= ((unsigned)d) << shift;
        }
        __syncthreads();
    }
}

// ---------------- compact all keys >= threshold (ties included) ----------------
__global__ void compact_k() {
    int tid = threadIdx.x;
    int b = blockIdx.y;
    unsigned T = g_prefix[b];
    const uint4* k4 = (const uint4*)g_keys + (size_t)b * (NN / 4);
#pragma unroll
    for (int t = 0; t < 4; t++) {
        int f = blockIdx.x * 1024 + t * 256 + tid;
        uint4 v = k4[f];
        unsigned a[4] = {v.x, v.y, v.z, v.w};
#pragma unroll
        for (int e = 0; e < 4; e++) {
            if (a[e] >= T) {
                int pos = atomicAdd(&g_cnt[b], 1);
                if (pos < SEL_CAP)
                    g_sel[b * SEL_CAP + pos] =
                        (((unsigned long long)(~a[e])) << 32) | (unsigned)(f * 4 + e);
            }
        }
    }
}

// ---------------- bitonic sort (score desc, idx asc) + gather + box decode ----------------
// one block per batch, 1024 threads, dynamic smem = SEL_CAP*8 bytes
__global__ void sort_decode_k(const float* __restrict__ bbox,
                              const float* __restrict__ anchors) {
    extern __shared__ unsigned long long a[];
    int tid = threadIdx.x, b = blockIdx.x;
    int cnt = g_cnt[b];
    if (cnt > SEL_CAP) cnt = SEL_CAP;
    for (int i = tid; i < SEL_CAP; i += blockDim.x)
        a[i] = (i < cnt) ? g_sel[b * SEL_CAP + i] : 0xFFFFFFFFFFFFFFFFull;
    __syncthreads();
    for (int k = 2; k <= SEL_CAP; k <<= 1)
        for (int j = k >> 1; j > 0; j >>= 1) {
            for (int i = tid; i < SEL_CAP; i += blockDim.x) {
                int ix = i ^ j;
                if (ix > i) {
                    unsigned long long x = a[i], y = a[ix];
                    bool up = ((i & k) == 0);
                    if ((x > y) == up) { a[i] = y; a[ix] = x; }
                }
            }
            __syncthreads();
        }
    // first PRE entries = top-k sorted (score desc, idx asc). decode boxes.
    for (int r = tid; r < PRE; r += blockDim.x) {
        unsigned idx = (unsigned)a[r];
        float4 A = ((const float4*)anchors)[(size_t)b * NN + idx];
        float4 D = ((const float4*)bbox)[(size_t)b * NN + idx];
        float y1 = A.x, x1 = A.y, y2 = A.z, x2 = A.w;
        float h = __fsub_rn(y2, y1), w = __fsub_rn(x2, x1);
        float cy = __fadd_rn(y1, __fmul_rn(0.5f, h));
        float cx = __fadd_rn(x1, __fmul_rn(0.5f, w));
        float d0 = __fmul_rn(D.x, 0.1f), d1 = __fmul_rn(D.y, 0.1f);
        float d2 = __fmul_rn(D.z, 0.2f), d3 = __fmul_rn(D.w, 0.2f);
        cy = __fadd_rn(cy, __fmul_rn(d0, h));
        cx = __fadd_rn(cx, __fmul_rn(d1, w));
        h = __fmul_rn(h, expf(d2));
        w = __fmul_rn(w, expf(d3));
        float ny1 = __fsub_rn(cy, __fmul_rn(0.5f, h));
        float nx1 = __fsub_rn(cx, __fmul_rn(0.5f, w));
        float ny2 = __fadd_rn(cy, __fmul_rn(0.5f, h));
        float nx2 = __fadd_rn(cx, __fmul_rn(0.5f, w));
        ny1 = fminf(fmaxf(ny1, 0.f), 1.f);
        nx1 = fminf(fmaxf(nx1, 0.f), 1.f);
        ny2 = fminf(fmaxf(ny2, 0.f), 1.f);
        nx2 = fminf(fmaxf(nx2, 0.f), 1.f);
        g_boxes[b * PRE + r] = make_float4(ny1, nx1, ny2, nx2);
    }
}

// ---------------- candidate-validation greedy NMS ----------------
// one block per batch, 1024 threads, dyn smem = PRE*16 bytes.
// thread t keeps the t-th SELECTED box in registers; each candidate is validated
// against all selected boxes with one IoU per thread + a single __syncthreads_or.
__global__ void nms_k(float* __restrict__ out) {
    extern __shared__ float4 sb[];   // 6000 candidate boxes
    int tid = threadIdx.x, b = blockIdx.x;
    for (int i = tid; i < PRE; i += blockDim.x) sb[i] = g_boxes[b * PRE + i];
    __syncthreads();

    float4 mysel = make_float4(0.f, 0.f, 0.f, 0.f);
    float myarea = 0.f;
    int k = 0;
    float4* outp = (float4*)out + (size_t)b * PROP;

    for (int cand = 0; cand < PRE; cand++) {
        float4 c = sb[cand];   // LDS broadcast
        int pred = 0;
        if (tid < k) {
            float iy1 = fmaxf(c.x, mysel.x), ix1 = fmaxf(c.y, mysel.y);
            float iy2 = fminf(c.z, mysel.z), ix2 = fminf(c.w, mysel.w);
            float ih = fmaxf(__fsub_rn(iy2, iy1), 0.f);
            float iw = fmaxf(__fsub_rn(ix2, ix1), 0.f);
            float inter = __fmul_rn(ih, iw);
            float areaC = __fmul_rn(__fsub_rn(c.z, c.x), __fsub_rn(c.w, c.y));
            float uni = __fsub_rn(__fadd_rn(myarea, areaC), inter);
            float iou = __fdiv_rn(inter, fmaxf(uni, 1e-10f));
            pred = (iou > 0.7f);
        }
        int rej = __syncthreads_or(pred);
        if (!rej) {
            if (tid == k) {
                mysel = c;
                myarea = __fmul_rn(__fsub_rn(c.z, c.x), __fsub_rn(c.w, c.y));
            }
            if (tid == 0) outp[k] = c;
            k++;
            if (k == PROP) break;
        }
    }
    // pad remaining proposals with zeros (reference semantics)
    for (int r = k + tid; r < PROP; r += blockDim.x)
        outp[r] = make_float4(0.f, 0.f, 0.f, 0.f);
}

// ---------------- launch ----------------
extern "C" void kernel_launch(void* const* d_in, const int* in_sizes, int n_in,
                              void* d_out, int out_size) {
    const float* probs   = (const float*)d_in[0];
    const float* bbox    = (const float*)d_in[1];
    const float* anchors = (const float*)d_in[2];
    float* out = (float*)d_out;

    cudaFuncSetAttribute(sort_decode_k, cudaFuncAttributeMaxDynamicSharedMemorySize, SEL_CAP * 8);
    cudaFuncSetAttribute(nms_k,         cudaFuncAttributeMaxDynamicSharedMemorySize, PRE * 16);

    init_k<<<8, 256>>>();
    dim3 ge(128, BATCH);
    extract_hist_k<<<ge, 256>>>(probs);
    select_k<<<1, 256>>>(24);
    dim3 gh(64, BATCH);
    hist_k<<<gh, 256>>>(16);
    select_k<<<1, 256>>>(16);
    hist_k<<<gh, 256>>>(8);
    select_k<<<1, 256>>>(8);
    hist_k<<<gh, 256>>>(0);
    select_k<<<1, 256>>>(0);
    compact_k<<<gh, 256>>>();
    sort_decode_k<<<BATCH, 1024, SEL_CAP * 8>>>(bbox, anchors);
    nms_k<<<BATCH, 1024, PRE * 16>>>(out);
}

// round 2
// speedup vs baseline: 1.9434x; 1.9434x over previous
#include <cuda_runtime.h>
#include <math.h>

#define BATCH 8
#define NN 262144
#define PRE 6000
#define PROP 1000
#define SEL_CAP 8192
#define CMASK 1024                      // candidates covered by the bitmask NMS
#define MWORDS (CMASK / 32)             // 32 words per mask row

// ---------------- scratch (static device memory; no allocations) ----------------
__device__ unsigned int       g_keys[BATCH * NN];            // 8 MB
__device__ int                g_hist[BATCH * 256];
__device__ unsigned int       g_prefix[BATCH];
__device__ int                g_krem[BATCH];
__device__ int                g_cnt[BATCH];
__device__ unsigned long long g_sel[BATCH * SEL_CAP];        // 512 KB
__device__ float4             g_boxes[BATCH * PRE];          // 768 KB
__device__ unsigned int       g_mask[BATCH * CMASK * MWORDS];// 1 MB

// order-preserving float -> uint key
__device__ __forceinline__ unsigned fkey(float f) {
    unsigned u = __float_as_uint(f);
    return u ^ (((unsigned)((int)u >> 31)) | 0x80000000u);
}

// ---------------- init ----------------
__global__ void init_k() {
    int t = blockIdx.x * blockDim.x + threadIdx.x;
    if (t < BATCH * 256) g_hist[t] = 0;
    if (t < BATCH) { g_prefix[t] = 0; g_krem[t] = PRE; g_cnt[t] = 0; }
}

// ---------------- pass 0: extract keys + histogram of top byte ----------------
__global__ void extract_hist_k(const float* __restrict__ probs) {
    __shared__ int sh[256];
    int tid = threadIdx.x;
    sh[tid] = 0;
    __syncthreads();
    int b = blockIdx.y;
    const float4* p4 = (const float4*)probs + (size_t)b * (NN / 2);
    uint2* kout = (uint2*)g_keys + (size_t)b * (NN / 2);
#pragma unroll
    for (int t = 0; t < 4; t++) {
        int f = blockIdx.x * 1024 + t * 256 + tid;
        float4 v = p4[f];
        unsigned k0 = fkey(v.y), k1 = fkey(v.w);
        kout[f] = make_uint2(k0, k1);
        atomicAdd(&sh[k0 >> 24], 1);
        atomicAdd(&sh[k1 >> 24], 1);
    }
    __syncthreads();
    if (sh[tid]) atomicAdd(&g_hist[b * 256 + tid], sh[tid]);
}

// ---------------- radix pass histogram ----------------
__global__ void hist_k(int shift) {
    __shared__ int sh[256];
    int tid = threadIdx.x;
    sh[tid] = 0;
    __syncthreads();
    int b = blockIdx.y;
    unsigned pref = g_prefix[b];
    unsigned mh = 0xFFFFFFFFu << (shift + 8);
    const uint4* k4 = (const uint4*)g_keys + (size_t)b * (NN / 4);
#pragma unroll
    for (int t = 0; t < 4; t++) {
        int f = blockIdx.x * 1024 + t * 256 + tid;
        uint4 v = k4[f];
        unsigned a[4] = {v.x, v.y, v.z, v.w};
#pragma unroll
        for (int e = 0; e < 4; e++)
            if ((a[e] & mh) == (pref & mh))
                atomicAdd(&sh[(a[e] >> shift) & 0xFF], 1);
    }
    __syncthreads();
    if (sh[tid]) atomicAdd(&g_hist[b * 256 + tid], sh[tid]);
}

// ---------------- pick bucket containing k-th largest ----------------
__global__ void select_k(int shift) {
    __shared__ int h[256];
    int tid = threadIdx.x;
    for (int b = 0; b < BATCH; b++) {
        h[tid] = g_hist[b * 256 + tid];
        g_hist[b * 256 + tid] = 0;
        __syncthreads();
        if (tid == 0) {
            int krem = g_krem[b], acc = 0, d = 255;
            for (; d > 0; d--) {
                int c = h[d];
                if (acc + c >= krem) break;
                acc += c;
            }
            g_krem[b] = krem - acc;
            g_prefix[b] |= ((unsigned)d) << shift;
        }
        __syncthreads();
    }
}

// ---------------- compact all keys >= threshold ----------------
__global__ void compact_k() {
    int tid = threadIdx.x;
    int b = blockIdx.y;
    unsigned T = g_prefix[b];
    const uint4* k4 = (const uint4*)g_keys + (size_t)b * (NN / 4);
#pragma unroll
    for (int t = 0; t < 4; t++) {
        int f = blockIdx.x * 1024 + t * 256 + tid;
        uint4 v = k4[f];
        unsigned a[4] = {v.x, v.y, v.z, v.w};
#pragma unroll
        for (int e = 0; e < 4; e++) {
            if (a[e] >= T) {
                int pos = atomicAdd(&g_cnt[b], 1);
                if (pos < SEL_CAP)
                    g_sel[b * SEL_CAP + pos] =
                        (((unsigned long long)(~a[e])) << 32) | (unsigned)(f * 4 + e);
            }
        }
    }
}

// ---------------- bitonic sort (score desc, idx asc) + gather + box decode ----------------
__global__ void __launch_bounds__(1024, 1)
sort_decode_k(const float* __restrict__ bbox, const float* __restrict__ anchors) {
    extern __shared__ unsigned long long a[];
    int tid = threadIdx.x, b = blockIdx.x;
    int cnt = g_cnt[b];
    if (cnt > SEL_CAP) cnt = SEL_CAP;
    for (int i = tid; i < SEL_CAP; i += 1024)
        a[i] = (i < cnt) ? g_sel[b * SEL_CAP + i] : 0xFFFFFFFFFFFFFFFFull;
    __syncthreads();
    for (int k = 2; k <= SEL_CAP; k <<= 1)
        for (int j = k >> 1; j > 0; j >>= 1) {
            // pair-slot formulation: all 4096 pairs active
#pragma unroll 4
            for (int m = tid; m < SEL_CAP / 2; m += 1024) {
                int i = ((m & ~(j - 1)) << 1) | (m & (j - 1));
                int ix = i | j;
                unsigned long long x = a[i], y = a[ix];
                bool up = ((i & k) == 0);
                if ((x > y) == up) { a[i] = y; a[ix] = x; }
            }
            __syncthreads();
        }
    // decode top PRE boxes
    for (int r = tid; r < PRE; r += 1024) {
        unsigned idx = (unsigned)a[r];
        float4 A = ((const float4*)anchors)[(size_t)b * NN + idx];
        float4 D = ((const float4*)bbox)[(size_t)b * NN + idx];
        float y1 = A.x, x1 = A.y, y2 = A.z, x2 = A.w;
        float h = __fsub_rn(y2, y1), w = __fsub_rn(x2, x1);
        float cy = __fadd_rn(y1, __fmul_rn(0.5f, h));
        float cx = __fadd_rn(x1, __fmul_rn(0.5f, w));
        float d0 = __fmul_rn(D.x, 0.1f), d1 = __fmul_rn(D.y, 0.1f);
        float d2 = __fmul_rn(D.z, 0.2f), d3 = __fmul_rn(D.w, 0.2f);
        cy = __fadd_rn(cy, __fmul_rn(d0, h));
        cx = __fadd_rn(cx, __fmul_rn(d1, w));
        h = __fmul_rn(h, expf(d2));
        w = __fmul_rn(w, expf(d3));
        float ny1 = __fsub_rn(cy, __fmul_rn(0.5f, h));
        float nx1 = __fsub_rn(cx, __fmul_rn(0.5f, w));
        float ny2 = __fadd_rn(cy, __fmul_rn(0.5f, h));
        float nx2 = __fadd_rn(cx, __fmul_rn(0.5f, w));
        ny1 = fminf(fmaxf(ny1, 0.f), 1.f);
        nx1 = fminf(fmaxf(nx1, 0.f), 1.f);
        ny2 = fminf(fmaxf(ny2, 0.f), 1.f);
        nx2 = fminf(fmaxf(nx2, 0.f), 1.f);
        g_boxes[b * PRE + r] = make_float4(ny1, nx1, ny2, nx2);
    }
}

// ---------------- suppression IoU helper (matches reference fp semantics) ----------------
__device__ __forceinline__ int suppresses(float4 s, float sArea, float4 c) {
    float iy1 = fmaxf(c.x, s.x), ix1 = fmaxf(c.y, s.y);
    float iy2 = fminf(c.z, s.z), ix2 = fminf(c.w, s.w);
    float ih = fmaxf(__fsub_rn(iy2, iy1), 0.f);
    float iw = fmaxf(__fsub_rn(ix2, ix1), 0.f);
    float inter = __fmul_rn(ih, iw);
    float areaC = __fmul_rn(__fsub_rn(c.z, c.x), __fsub_rn(c.w, c.y));
    float uni = __fsub_rn(__fadd_rn(sArea, areaC), inter);
    float iou = __fdiv_rn(inter, fmaxf(uni, 1e-10f));
    return iou > 0.7f;
}

// ---------------- IoU suppression bit-matrix for first CMASK candidates ----------------
// one thread per 32-bit mask word: word (i, wj) = bits of candidates j in [wj*32, wj*32+32), j>i
__global__ void iou_mask_k() {
    int b = blockIdx.y;
    int w = blockIdx.x * 256 + threadIdx.x;       // 0 .. CMASK*MWORDS-1
    int i = w >> 5;                                // row (suppressor candidate)
    int wj = w & (MWORDS - 1);
    float4 s = g_boxes[b * PRE + i];
    float sArea = __fmul_rn(__fsub_rn(s.z, s.x), __fsub_rn(s.w, s.y));
    unsigned bits = 0;
    int base = wj * 32;
    if (base + 31 > i) {                           // row has any j>i in this word
#pragma unroll 8
        for (int bb = 0; bb < 32; bb++) {
            int j = base + bb;
            if (j > i) {
                float4 c = g_boxes[b * PRE + j];
                if (suppresses(s, sArea, c)) bits |= (1u << bb);
            }
        }
    }
    g_mask[(b * CMASK + i) * MWORDS + wj] = bits;
}

// ---------------- NMS walk (bitmask phase + register-validation fallback) ----------------
// one block per batch, 1024 threads.
// dyn smem: mask[CMASK*MWORDS] + active[MWORDS pad 32] + selids[PROP] + kshare
#define SMEM_WALK (CMASK * MWORDS * 4 + 32 * 4 + PROP * 4 + 16)

__global__ void __launch_bounds__(1024, 1) nms_walk_k(float* __restrict__ out) {
    extern __shared__ unsigned sm[];
    unsigned* smask  = sm;                          // CMASK*MWORDS
    unsigned* active = sm + CMASK * MWORDS;         // 32
    int* selids      = (int*)(active + 32);         // PROP
    int* kshare      = selids + PROP;

    int tid = threadIdx.x, b = blockIdx.x;

    // preload mask into shared (coalesced, high MLP)
    const unsigned* gm = &g_mask[b * CMASK * MWORDS];
#pragma unroll
    for (int i = tid; i < CMASK * MWORDS; i += 1024) smask[i] = gm[i];
    if (tid < 32) active[tid] = 0xFFFFFFFFu;
    __syncthreads();

    // ---- phase 1: serial walk by warp 0 ----
    if (tid < 32) {
        int lane = tid;
        unsigned aw = active[lane];   // each lane owns 32 candidates
        int k = 0;
        while (true) {
            int pos = aw ? (lane * 32 + __ffs(aw) - 1) : (1 << 30);
            int cand = __reduce_min_sync(0xFFFFFFFFu, pos);
            if (cand >= CMASK) break;
            if (lane == 0) selids[k] = cand;
            k++;
            unsigned row = smask[cand * MWORDS + lane];
            aw &= ~row;
            if (lane == (cand >> 5)) aw &= ~(1u << (cand & 31));
            if (k == PROP) break;
        }
        if (lane == 0) *kshare = k;
    }
    __syncthreads();
    int k = *kshare;

    // ---- phase 2: fallback over candidates >= CMASK (rare) ----
    if (k < PROP) {
        float4 mysel = make_float4(0.f, 0.f, 0.f, 0.f);
        float myarea = 0.f;
        if (tid < k) {
            mysel = g_boxes[b * PRE + selids[tid]];
            myarea = __fmul_rn(__fsub_rn(mysel.z, mysel.x), __fsub_rn(mysel.w, mysel.y));
        }
        __syncthreads();
        for (int cand = CMASK; cand < PRE; cand++) {
            float4 c = g_boxes[b * PRE + cand];
            int pred = 0;
            if (tid < k) pred = suppresses(mysel, myarea, c);
            int rej = __syncthreads_or(pred);
            if (!rej) {
                if (tid == k) {
                    mysel = c;
                    myarea = __fmul_rn(__fsub_rn(c.z, c.x), __fsub_rn(c.w, c.y));
                }
                if (tid == 0) selids[k] = cand;
                k++;
                if (k == PROP) break;
            }
        }
        __syncthreads();
    }

    // ---- phase 3: write output ----
    float4* outp = (float4*)out + (size_t)b * PROP;
    if (tid < PROP) {
        if (tid < k) outp[tid] = g_boxes[b * PRE + selids[tid]];
        else         outp[tid] = make_float4(0.f, 0.f, 0.f, 0.f);
    }
}

// ---------------- launch ----------------
extern "C" void kernel_launch(void* const* d_in, const int* in_sizes, int n_in,
                              void* d_out, int out_size) {
    const float* probs   = (const float*)d_in[0];
    const float* bbox    = (const float*)d_in[1];
    const float* anchors = (const float*)d_in[2];
    float* out = (float*)d_out;

    cudaFuncSetAttribute(sort_decode_k, cudaFuncAttributeMaxDynamicSharedMemorySize, SEL_CAP * 8);
    cudaFuncSetAttribute(nms_walk_k,    cudaFuncAttributeMaxDynamicSharedMemorySize, SMEM_WALK);

    init_k<<<8, 256>>>();
    dim3 ge(128, BATCH);
    extract_hist_k<<<ge, 256>>>(probs);
    select_k<<<1, 256>>>(24);
    dim3 gh(64, BATCH);
    hist_k<<<gh, 256>>>(16);
    select_k<<<1, 256>>>(16);
    hist_k<<<gh, 256>>>(8);
    select_k<<<1, 256>>>(8);
    hist_k<<<gh, 256>>>(0);
    select_k<<<1, 256>>>(0);
    compact_k<<<gh, 256>>>();
    sort_decode_k<<<BATCH, 1024, SEL_CAP * 8>>>(bbox, anchors);
    dim3 gi((CMASK * MWORDS) / 256, BATCH);
    iou_mask_k<<<gi, 256>>>();
    nms_walk_k<<<BATCH, 1024, SMEM_WALK>>>(out);
}

// round 3
// speedup vs baseline: 2.6810x; 1.3796x over previous
#include <cuda_runtime.h>
#include <math.h>

#define BATCH 8
#define NN 262144
#define PRE 6000
#define PROP 1000
#define SEL_CAP 8192
#define CMASK 1024
#define MWORDS (CMASK / 32)

// ---------------- scratch ----------------
__device__ unsigned int       g_keys[BATCH * NN];             // 8 MB
__device__ int                g_h16[BATCH * 65536];           // 2 MB
__device__ unsigned int       g_thr[BATCH];
__device__ int                g_cnt[BATCH];
__device__ unsigned long long g_sel[BATCH * SEL_CAP];
__device__ float4             g_boxes[BATCH * PRE];
__device__ unsigned int       g_mask[BATCH * CMASK * MWORDS]; // 1 MB

__device__ __forceinline__ unsigned fkey(float f) {
    unsigned u = __float_as_uint(f);
    return u ^ (((unsigned)((int)u >> 31)) | 0x80000000u);
}

// ---------------- zero state ----------------
__global__ void zero_k() {
    int t = blockIdx.x * blockDim.x + threadIdx.x;
    int n = BATCH * 65536;
    for (int i = t; i < n; i += gridDim.x * blockDim.x) g_h16[i] = 0;
    if (t < BATCH) g_cnt[t] = 0;
}

// ---------------- extract keys + 16-bit histogram ----------------
__global__ void extract_hist16_k(const float* __restrict__ probs) {
    int tid = threadIdx.x, b = blockIdx.y;
    const float4* p4 = (const float4*)probs + (size_t)b * (NN / 2);
    uint2* kout = (uint2*)g_keys + (size_t)b * (NN / 2);
    int* h = &g_h16[b * 65536];
#pragma unroll
    for (int t = 0; t < 4; t++) {
        int f = blockIdx.x * 1024 + t * 256 + tid;
        float4 v = p4[f];
        unsigned k0 = fkey(v.y), k1 = fkey(v.w);
        kout[f] = make_uint2(k0, k1);
        atomicAdd(&h[k0 >> 16], 1);
        atomicAdd(&h[k1 >> 16], 1);
    }
}

// ---------------- select 16-bit threshold bin ----------------
__global__ void select16_k() {
    __shared__ int part[1024];
    int tid = threadIdx.x, b = blockIdx.x;
    const int* h = &g_h16[b * 65536];
    int s = 0, base = tid * 64;
#pragma unroll 8
    for (int q = 0; q < 64; q++) s += h[base + q];
    part[tid] = s;
    __syncthreads();
    if (tid == 0) {
        int acc = 0, t = 1023;
        for (; t > 0; t--) {
            int c = part[t];
            if (acc + c >= PRE) break;
            acc += c;
        }
        int bin = t * 64 + 63;
        for (; bin > 0; bin--) {
            int c = h[bin];
            if (acc + c >= PRE) break;
            acc += c;
        }
        g_thr[b] = ((unsigned)bin) << 16;
    }
}

// ---------------- compact all keys >= threshold ----------------
__global__ void compact_k() {
    int tid = threadIdx.x, b = blockIdx.y;
    unsigned T = g_thr[b];
    const uint4* k4 = (const uint4*)g_keys + (size_t)b * (NN / 4);
#pragma unroll
    for (int t = 0; t < 4; t++) {
        int f = blockIdx.x * 1024 + t * 256 + tid;
        uint4 v = k4[f];
        unsigned a[4] = {v.x, v.y, v.z, v.w};
#pragma unroll
        for (int e = 0; e < 4; e++) {
            if (a[e] >= T) {
                int pos = atomicAdd(&g_cnt[b], 1);
                if (pos < SEL_CAP)
                    g_sel[b * SEL_CAP + pos] =
                        (((unsigned long long)(~a[e])) << 32) | (unsigned)(f * 4 + e);
            }
        }
    }
}

// ---------------- register-batched bitonic sort + decode ----------------
__device__ __forceinline__ void cswap(unsigned long long& x, unsigned long long& y, bool up) {
    if ((x > y) == up) { unsigned long long t = x; x = y; y = t; }
}

__global__ void __launch_bounds__(1024, 1)
sort_decode_k(const float* __restrict__ bbox, const float* __restrict__ anchors) {
    extern __shared__ unsigned long long a[];
    int tid = threadIdx.x, b = blockIdx.x;
    int cnt = g_cnt[b];
    if (cnt > SEL_CAP) cnt = SEL_CAP;
    for (int i = tid; i < SEL_CAP; i += 1024)
        a[i] = (i < cnt) ? g_sel[b * SEL_CAP + i] : 0xFFFFFFFFFFFFFFFFull;
    __syncthreads();

    unsigned long long v[8];
    int base = tid * 8;

    // initial k=2,4,8 phases entirely in registers
#pragma unroll
    for (int e = 0; e < 8; e++) v[e] = a[base + e];
#pragma unroll
    for (int k = 2; k <= 8; k <<= 1) {
#pragma unroll
        for (int j = k >> 1; j > 0; j >>= 1) {
#pragma unroll
            for (int e = 0; e < 8; e++) {
                int ex = e ^ j;
                if (ex > e) cswap(v[e], v[ex], ((base + e) & k) == 0);
            }
        }
    }
#pragma unroll
    for (int e = 0; e < 8; e++) a[base + e] = v[e];
    __syncthreads();

    for (int k = 16; k <= SEL_CAP; k <<= 1) {
        for (int j = k >> 1; j >= 8; j >>= 1) {
#pragma unroll 4
            for (int m = tid; m < SEL_CAP / 2; m += 1024) {
                int i = ((m & ~(j - 1)) << 1) | (m & (j - 1));
                int ix = i | j;
                unsigned long long x = a[i], y = a[ix];
                if ((x > y) == ((i & k) == 0)) { a[i] = y; a[ix] = x; }
            }
            __syncthreads();
        }
        // j = 4,2,1 in registers; direction uniform per thread (k >= 16)
        bool up = ((base & k) == 0);
#pragma unroll
        for (int e = 0; e < 8; e++) v[e] = a[base + e];
#pragma unroll
        for (int j = 4; j > 0; j >>= 1) {
#pragma unroll
            for (int e = 0; e < 8; e++) {
                int ex = e ^ j;
                if (ex > e) cswap(v[e], v[ex], up);
            }
        }
#pragma unroll
        for (int e = 0; e < 8; e++) a[base + e] = v[e];
        __syncthreads();
    }

    // decode top PRE boxes
    for (int r = tid; r < PRE; r += 1024) {
        unsigned idx = (unsigned)a[r];
        float4 A = ((const float4*)anchors)[(size_t)b * NN + idx];
        float4 D = ((const float4*)bbox)[(size_t)b * NN + idx];
        float y1 = A.x, x1 = A.y, y2 = A.z, x2 = A.w;
        float h = __fsub_rn(y2, y1), w = __fsub_rn(x2, x1);
        float cy = __fadd_rn(y1, __fmul_rn(0.5f, h));
        float cx = __fadd_rn(x1, __fmul_rn(0.5f, w));
        float d0 = __fmul_rn(D.x, 0.1f), d1 = __fmul_rn(D.y, 0.1f);
        float d2 = __fmul_rn(D.z, 0.2f), d3 = __fmul_rn(D.w, 0.2f);
        cy = __fadd_rn(cy, __fmul_rn(d0, h));
        cx = __fadd_rn(cx, __fmul_rn(d1, w));
        h = __fmul_rn(h, expf(d2));
        w = __fmul_rn(w, expf(d3));
        float ny1 = __fsub_rn(cy, __fmul_rn(0.5f, h));
        float nx1 = __fsub_rn(cx, __fmul_rn(0.5f, w));
        float ny2 = __fadd_rn(cy, __fmul_rn(0.5f, h));
        float nx2 = __fadd_rn(cx, __fmul_rn(0.5f, w));
        ny1 = fminf(fmaxf(ny1, 0.f), 1.f);
        nx1 = fminf(fmaxf(nx1, 0.f), 1.f);
        ny2 = fminf(fmaxf(ny2, 0.f), 1.f);
        nx2 = fminf(fmaxf(nx2, 0.f), 1.f);
        g_boxes[b * PRE + r] = make_float4(ny1, nx1, ny2, nx2);
    }
}

// ---------------- suppression IoU ----------------
__device__ __forceinline__ int suppresses(float4 s, float sArea, float4 c) {
    float iy1 = fmaxf(c.x, s.x), ix1 = fmaxf(c.y, s.y);
    float iy2 = fminf(c.z, s.z), ix2 = fminf(c.w, s.w);
    float ih = fmaxf(__fsub_rn(iy2, iy1), 0.f);
    float iw = fmaxf(__fsub_rn(ix2, ix1), 0.f);
    float inter = __fmul_rn(ih, iw);
    float areaC = __fmul_rn(__fsub_rn(c.z, c.x), __fsub_rn(c.w, c.y));
    float uni = __fsub_rn(__fadd_rn(sArea, areaC), inter);
    float iou = __fdiv_rn(inter, fmaxf(uni, 1e-10f));
    return iou > 0.7f;
}

// ---------------- IoU suppression bit-matrix ----------------
__global__ void iou_mask_k() {
    int b = blockIdx.y;
    int w = blockIdx.x * 256 + threadIdx.x;
    int i = w >> 5;
    int wj = w & (MWORDS - 1);
    float4 s = g_boxes[b * PRE + i];
    float sArea = __fmul_rn(__fsub_rn(s.z, s.x), __fsub_rn(s.w, s.y));
    unsigned bits = 0;
    int basej = wj * 32;
    if (basej + 31 > i) {
#pragma unroll 8
        for (int bb = 0; bb < 32; bb++) {
            int j = basej + bb;
            if (j > i) {
                float4 c = g_boxes[b * PRE + j];
                if (suppresses(s, sArea, c)) bits |= (1u << bb);
            }
        }
    }
    g_mask[(b * CMASK + i) * MWORDS + wj] = bits;
}

// ---------------- block-sequential parallel NMS resolve ----------------
// dyn smem layout: smask[CMASK*MWORDS] | supArr[32] | awords[32] | wpref[33] | selids[PROP] | misc
#define SMEM_RESOLVE (CMASK * MWORDS * 4 + 32 * 4 + 32 * 4 + 33 * 4 + PROP * 4 + 32)

__global__ void __launch_bounds__(1024, 1) nms_resolve_k(float* __restrict__ out) {
    extern __shared__ unsigned sm[];
    unsigned* smask  = sm;                          // CMASK*MWORDS
    unsigned* supArr = sm + CMASK * MWORDS;         // 32
    unsigned* awords = supArr + 32;                 // 32
    int* wpref       = (int*)(awords + 32);         // 33
    int* selids      = wpref + 33;                  // PROP

    int tid = threadIdx.x, b = blockIdx.x;

    const unsigned* gm = &g_mask[b * CMASK * MWORDS];
#pragma unroll
    for (int i = tid; i < CMASK * MWORDS; i += 1024) smask[i] = gm[i];
    if (tid < 32) { supArr[tid] = 0; awords[tid] = 0xFFFFFFFFu; }
    __syncthreads();

    // sequential over 32 candidate blocks; parallel within
    for (int B = 0; B < MWORDS; B++) {
        // cross-block suppression: OR mask word B over alive earlier candidates
        unsigned contrib = 0;
        if (tid < B * 32) {
            if ((awords[tid >> 5] >> (tid & 31)) & 1u)
                contrib = smask[tid * MWORDS + B];
        }
        contrib = __reduce_or_sync(0xFFFFFFFFu, contrib);
        if ((tid & 31) == 0 && contrib) atomicOr(&supArr[B], contrib);
        __syncthreads();
        // within-block resolution by warp 0 (ballot-guided, usually 0-1 iters)
        if (tid < 32) {
            unsigned myrow = smask[(B * 32 + tid) * MWORDS + B];
            unsigned aliveB = ~supArr[B];
            unsigned candm = __ballot_sync(0xFFFFFFFFu, myrow != 0);
            while (true) {
                unsigned act = candm & aliveB;
                if (!act) break;
                int bs = __ffs(act) - 1;
                unsigned rowW = __shfl_sync(0xFFFFFFFFu, myrow, bs);
                aliveB &= ~rowW;
                candm &= ~(1u << bs);
            }
            if (tid == 0) awords[B] = aliveB;
        }
        __syncthreads();
    }

    // ranks of alive candidates
    if (tid == 0) {
        int acc = 0;
        for (int wq = 0; wq < 32; wq++) { wpref[wq] = acc; acc += __popc(awords[wq]); }
        wpref[32] = acc;
    }
    __syncthreads();
    if (tid < CMASK) {
        unsigned wv = awords[tid >> 5];
        if ((wv >> (tid & 31)) & 1u) {
            int rank = wpref[tid >> 5] + __popc(wv & ((1u << (tid & 31)) - 1u));
            if (rank < PROP) selids[rank] = tid;
        }
    }
    __syncthreads();
    int k = wpref[32];
    if (k > PROP) k = PROP;

    // fallback beyond CMASK (rare)
    if (k < PROP) {
        float4 mysel = make_float4(0.f, 0.f, 0.f, 0.f);
        float myarea = 0.f;
        if (tid < k) {
            mysel = g_boxes[b * PRE + selids[tid]];
            myarea = __fmul_rn(__fsub_rn(mysel.z, mysel.x), __fsub_rn(mysel.w, mysel.y));
        }
        __syncthreads();
        for (int cand = CMASK; cand < PRE; cand++) {
            float4 c = g_boxes[b * PRE + cand];
            int pred = 0;
            if (tid < k) pred = suppresses(mysel, myarea, c);
            int rej = __syncthreads_or(pred);
            if (!rej) {
                if (tid == k) {
                    mysel = c;
                    myarea = __fmul_rn(__fsub_rn(c.z, c.x), __fsub_rn(c.w, c.y));
                }
                if (tid == 0) selids[k] = cand;
                k++;
                if (k == PROP) break;
            }
        }
        __syncthreads();
    }

    // output
    float4* outp = (float4*)out + (size_t)b * PROP;
    if (tid < PROP) {
        if (tid < k) outp[tid] = g_boxes[b * PRE + selids[tid]];
        else         outp[tid] = make_float4(0.f, 0.f, 0.f, 0.f);
    }
}

// ---------------- launch ----------------
extern "C" void kernel_launch(void* const* d_in, const int* in_sizes, int n_in,
                              void* d_out, int out_size) {
    const float* probs   = (const float*)d_in[0];
    const float* bbox    = (const float*)d_in[1];
    const float* anchors = (const float*)d_in[2];
    float* out = (float*)d_out;

    cudaFuncSetAttribute(sort_decode_k,  cudaFuncAttributeMaxDynamicSharedMemorySize, SEL_CAP * 8);
    cudaFuncSetAttribute(nms_resolve_k,  cudaFuncAttributeMaxDynamicSharedMemorySize, SMEM_RESOLVE);

    zero_k<<<512, 256>>>();
    dim3 ge(128, BATCH);
    extract_hist16_k<<<ge, 256>>>(probs);
    select16_k<<<BATCH, 1024>>>();
    dim3 gc(64, BATCH);
    compact_k<<<gc, 256>>>();
    sort_decode_k<<<BATCH, 1024, SEL_CAP * 8>>>(bbox, anchors);
    dim3 gi((CMASK * MWORDS) / 256, BATCH);
    iou_mask_k<<<gi, 256>>>();
    nms_resolve_k<<<BATCH, 1024, SMEM_RESOLVE>>>(out);
}